// round 11
// baseline (speedup 1.0000x reference)
#include <cuda_runtime.h>
#include <cstdint>

#define S_LEN 512
#define B_SZ  64
#define HIDD  1024
#define EMBD  512
#define NCLS  32000
#define FEATD 2048
#define RNN_NCTA 128
#define RNN_KS 8
// hshf [128k][64b] float = 32KB ; Wd dup [128k][128] float = 64KB
#define RNN_SMEM (128 * 64 * 4 + 128 * 128 * 4)

#define FFMA2(d, a, b) asm("fma.rn.f32x2 %0, %1, %2, %0;" : "+l"(d) : "l"(a), "l"(b))
union F2U { unsigned long long u; float2 f; };

// ---- device scratch ----
__device__ float g_G[(size_t)S_LEN * B_SZ * HIDD];
__device__ float g_OUT[(size_t)S_LEN * B_SZ * HIDD];
__device__ float g_Pb[2][RNN_KS * B_SZ * HIDD];     // double-buffered partials (2 x 2MB)
__device__ float g_h0[B_SZ * HIDD];
__device__ float g_scores[(S_LEN - 1) * B_SZ];
__device__ float g_attn[(S_LEN - 1) * B_SZ];
__device__ float g_attout[B_SZ * HIDD];
__device__ unsigned g_pcnt[16 * 32];   // per-jg producer counters, 128B apart
__device__ unsigned g_hcnt[16 * 32];   // per-jg combiner counters, 128B apart

__global__ void init_kernel() {
    int i = blockIdx.x * blockDim.x + threadIdx.x;
    if (i < B_SZ * HIDD) g_h0[i] = 0.f;
    if (i < 16 * 32) { g_pcnt[i] = 0u; g_hcnt[i] = 0u; }
}

// ---- K1: gates  G[(t*64+b)][j] = emb[X[b,t]] . W_ih[j] + b_ih[j] + b_hh[j] ----
__global__ void __launch_bounds__(256) gates_kernel(const int* __restrict__ X,
                                                    const float* __restrict__ emb,
                                                    const float* __restrict__ W_ih,
                                                    const float* __restrict__ b_ih,
                                                    const float* __restrict__ b_hh) {
    __shared__ float2 As2[16 * 64];
    __shared__ float  Bs[16 * 68];
    __shared__ int rowidx[64];
    const int n0 = blockIdx.x * 64;
    const int m0 = blockIdx.y * 64;
    const int tid = threadIdx.x;

    if (tid < 64) {
        int m = m0 + tid;
        int t = m >> 6, b = m & 63;
        rowidx[tid] = X[b * S_LEN + t];
    }
    __syncthreads();

    const int tx = tid & 15, ty = tid >> 4;
    unsigned long long acc[4][2];
#pragma unroll
    for (int i = 0; i < 4; i++) { acc[i][0] = 0ull; acc[i][1] = 0ull; }

    const int lm = tid >> 2;
    const int lk = (tid & 3) * 4;

    for (int k0 = 0; k0 < EMBD; k0 += 16) {
        float4 av = *(const float4*)&emb[(size_t)rowidx[lm] * EMBD + k0 + lk];
        As2[(lk + 0) * 64 + lm] = make_float2(av.x, av.x);
        As2[(lk + 1) * 64 + lm] = make_float2(av.y, av.y);
        As2[(lk + 2) * 64 + lm] = make_float2(av.z, av.z);
        As2[(lk + 3) * 64 + lm] = make_float2(av.w, av.w);
        float4 bv = *(const float4*)&W_ih[(size_t)(n0 + lm) * EMBD + k0 + lk];
        Bs[(lk + 0) * 68 + lm] = bv.x; Bs[(lk + 1) * 68 + lm] = bv.y;
        Bs[(lk + 2) * 68 + lm] = bv.z; Bs[(lk + 3) * 68 + lm] = bv.w;
        __syncthreads();
#pragma unroll
        for (int kk = 0; kk < 16; kk++) {
            ulonglong2 a01 = *(const ulonglong2*)&As2[kk * 64 + ty * 4];
            ulonglong2 a23 = *(const ulonglong2*)&As2[kk * 64 + ty * 4 + 2];
            ulonglong2 bp  = *(const ulonglong2*)&Bs[kk * 68 + tx * 4];
            FFMA2(acc[0][0], a01.x, bp.x); FFMA2(acc[0][1], a01.x, bp.y);
            FFMA2(acc[1][0], a01.y, bp.x); FFMA2(acc[1][1], a01.y, bp.y);
            FFMA2(acc[2][0], a23.x, bp.x); FFMA2(acc[2][1], a23.x, bp.y);
            FFMA2(acc[3][0], a23.y, bp.x); FFMA2(acc[3][1], a23.y, bp.y);
        }
        __syncthreads();
    }
    float4 bi = *(const float4*)&b_ih[n0 + tx * 4];
    float4 bh = *(const float4*)&b_hh[n0 + tx * 4];
    float bias[4] = {bi.x + bh.x, bi.y + bh.y, bi.z + bh.z, bi.w + bh.w};
#pragma unroll
    for (int i = 0; i < 4; i++) {
        int m = m0 + ty * 4 + i;
        F2U p0, p1; p0.u = acc[i][0]; p1.u = acc[i][1];
        float4 o = make_float4(p0.f.x + bias[0], p0.f.y + bias[1],
                               p1.f.x + bias[2], p1.f.y + bias[3]);
        *(float4*)&g_G[(size_t)m * HIDD + n0 + tx * 4] = o;
    }
}

// ---- point-to-point wait: tid0 spins on a monotonic counter ----
__device__ __forceinline__ void wait_ge(const unsigned* p, unsigned v) {
    if (threadIdx.x == 0) {
        while (*(volatile const unsigned*)p < v) __nanosleep(20);
    }
    __syncthreads();
    __threadfence();   // acquire-ish: order flag observation before data reads
}

// ---- K2: persistent recurrence, K-split 8, P2P flag sync (NO global barrier) ----
// CTA c: jg = c & 15 (64 j-cols), ks = c >> 4 (128 k each).
__global__ void __launch_bounds__(128, 1) rnn_kernel(const float* __restrict__ W_hh) {
    extern __shared__ char smem_raw[];
    float* hshf = (float*)smem_raw;                    // [128k][64b] undup
    float* Wd   = (float*)(smem_raw + 128 * 64 * 4);   // [128k][128] dup: Wd[k][2j]=(w,w)
    const int tid = threadIdx.x;
    const int c = blockIdx.x;
    const int jg = c & 15;   // 64 j-cols per group
    const int ks = c >> 4;   // 128 K each

    // resident W slice, k-major, duplicated
    {
        int jl = tid & 63;
        int kc = (tid >> 6) * 64;
        const float* wr = &W_hh[(size_t)(jg * 64 + jl) * HIDD + ks * 128 + kc];
#pragma unroll
        for (int q = 0; q < 16; q++) {
            float4 wv = *(const float4*)&wr[q * 4];
            *(float2*)&Wd[(kc + q * 4 + 0) * 128 + 2 * jl] = make_float2(wv.x, wv.x);
            *(float2*)&Wd[(kc + q * 4 + 1) * 128 + 2 * jl] = make_float2(wv.y, wv.y);
            *(float2*)&Wd[(kc + q * 4 + 2) * 128 + 2 * jl] = make_float2(wv.z, wv.z);
            *(float2*)&Wd[(kc + q * 4 + 3) * 128 + 2 * jl] = make_float2(wv.w, wv.w);
        }
    }
    __syncthreads();

    const int b0  = (tid & 7) * 8;    // 8 b's per thread
    const int jl0 = (tid >> 3) * 4;   // 4 j's per thread (local)
    const int sb  = tid & 63;         // staging batch
    const int skc = (tid >> 6) * 64;  // staging k-chunk
    // combine tile: b_off = tid>>4 (8 b's of range), j_off = (tid&15)*4
    const int cb = tid >> 4;
    const int cj = (tid & 15) * 4;

    for (int t = 0; t < S_LEN; ++t) {
        // ---- 1. wait for h chunks of our k-slice (combiners of jg 2ks, 2ks+1) ----
        if (t > 0) {
            wait_ge(&g_hcnt[(2 * ks) * 32],     8u * (unsigned)t);
            wait_ge(&g_hcnt[(2 * ks + 1) * 32], 8u * (unsigned)t);
        }
        // ---- 2. stage h(t-1) transposed: hshf[k*64+b] = h[b][k] ----
        {
            const float* hprev = (t == 0) ? g_h0 : (g_OUT + (size_t)(t - 1) * B_SZ * HIDD);
            const float* hr = &hprev[(size_t)sb * HIDD + ks * 128 + skc];
#pragma unroll
            for (int q = 0; q < 16; q++) {
                float4 hv = __ldcg((const float4*)&hr[q * 4]);
                hshf[(skc + q * 4 + 0) * 64 + sb] = hv.x;
                hshf[(skc + q * 4 + 1) * 64 + sb] = hv.y;
                hshf[(skc + q * 4 + 2) * 64 + sb] = hv.z;
                hshf[(skc + q * 4 + 3) * 64 + sb] = hv.w;
            }
        }
        __syncthreads();

        // ---- 3. compute partials: tile 8b x 4j ----
        unsigned long long acc[4][4];
#pragma unroll
        for (int i = 0; i < 4; i++)
#pragma unroll
            for (int p = 0; p < 4; p++) acc[i][p] = 0ull;

#pragma unroll 8
        for (int kk = 0; kk < 128; kk++) {
            ulonglong2 hA = *(const ulonglong2*)&hshf[kk * 64 + b0];
            ulonglong2 hB = *(const ulonglong2*)&hshf[kk * 64 + b0 + 4];
            ulonglong2 w01 = *(const ulonglong2*)&Wd[kk * 128 + 2 * jl0];
            ulonglong2 w23 = *(const ulonglong2*)&Wd[kk * 128 + 2 * jl0 + 4];
            FFMA2(acc[0][0], hA.x, w01.x); FFMA2(acc[0][1], hA.y, w01.x);
            FFMA2(acc[0][2], hB.x, w01.x); FFMA2(acc[0][3], hB.y, w01.x);
            FFMA2(acc[1][0], hA.x, w01.y); FFMA2(acc[1][1], hA.y, w01.y);
            FFMA2(acc[1][2], hB.x, w01.y); FFMA2(acc[1][3], hB.y, w01.y);
            FFMA2(acc[2][0], hA.x, w23.x); FFMA2(acc[2][1], hA.y, w23.x);
            FFMA2(acc[2][2], hB.x, w23.x); FFMA2(acc[2][3], hB.y, w23.x);
            FFMA2(acc[3][0], hA.x, w23.y); FFMA2(acc[3][1], hA.y, w23.y);
            FFMA2(acc[3][2], hB.x, w23.y); FFMA2(acc[3][3], hB.y, w23.y);
        }

        // ---- 4. WAR: our parity buffer must be consumed (combiners of jg done t-2) ----
        if (t >= 2) wait_ge(&g_hcnt[jg * 32], 8u * (unsigned)(t - 1));

        // ---- 5. write partials to g_Pb[t&1], publish to pcnt[jg] ----
        {
            float* pb = g_Pb[t & 1];
#pragma unroll
            for (int p = 0; p < 4; p++) {
                F2U a0, a1, a2, a3;
                a0.u = acc[0][p]; a1.u = acc[1][p]; a2.u = acc[2][p]; a3.u = acc[3][p];
                float4 lo = make_float4(a0.f.x, a1.f.x, a2.f.x, a3.f.x);
                float4 hi = make_float4(a0.f.y, a1.f.y, a2.f.y, a3.f.y);
                __stcg((float4*)&pb[ks * (B_SZ * HIDD) + (b0 + 2 * p) * HIDD + jg * 64 + jl0], lo);
                __stcg((float4*)&pb[ks * (B_SZ * HIDD) + (b0 + 2 * p + 1) * HIDD + jg * 64 + jl0], hi);
            }
        }
        __threadfence();
        __syncthreads();
        if (tid == 0) atomicAdd(&g_pcnt[jg * 32], 1u);

        // ---- 6. combine our b-range [ks*8, ks*8+8) x j-range [jg*64,+64) ----
        wait_ge(&g_pcnt[jg * 32], 8u * (unsigned)(t + 1));
        {
            const float* pb = g_Pb[t & 1];
            size_t off = (size_t)(ks * 8 + cb) * HIDD + jg * 64 + cj;
            float4 s = __ldcg((const float4*)&pb[off]);
#pragma unroll
            for (int sp = 1; sp < RNN_KS; sp++) {
                float4 p = __ldcg((const float4*)&pb[sp * (B_SZ * HIDD) + off]);
                s.x += p.x; s.y += p.y; s.z += p.z; s.w += p.w;
            }
            size_t gidx = (size_t)t * B_SZ * HIDD + off;
            float4 g = __ldcg((const float4*)&g_G[gidx]);
            float4 o;
            o.x = tanhf(g.x + s.x);
            o.y = tanhf(g.y + s.y);
            o.z = tanhf(g.z + s.z);
            o.w = tanhf(g.w + s.w);
            __stcg((float4*)&g_OUT[gidx], o);
        }
        __threadfence();
        __syncthreads();
        if (tid == 0) atomicAdd(&g_hcnt[jg * 32], 1u);
    }
}

// ---- K3a: scores ----
__global__ void __launch_bounds__(256) scores_kernel() {
    const int s = blockIdx.x;
    const int w = threadIdx.x >> 5, lane = threadIdx.x & 31;
    const float* Pv = g_OUT + (size_t)s * B_SZ * HIDD;
    const float* Lv = g_OUT + (size_t)(S_LEN - 1) * B_SZ * HIDD;
#pragma unroll
    for (int i = 0; i < 8; i++) {
        int b = w * 8 + i;
        const float* p = Pv + (size_t)b * HIDD;
        const float* l = Lv + (size_t)b * HIDD;
        float acc = 0.f;
#pragma unroll 4
        for (int k = lane; k < HIDD; k += 32) acc += p[k] * l[k];
#pragma unroll
        for (int o = 16; o > 0; o >>= 1) acc += __shfl_down_sync(0xffffffffu, acc, o);
        if (lane == 0) g_scores[s * B_SZ + b] = acc;
    }
}

// ---- K3b: softmax over s per b ----
__global__ void __launch_bounds__(512) softmax_kernel() {
    const int b = blockIdx.x;
    const int tid = threadIdx.x;
    __shared__ float red[512];
    float v = (tid < S_LEN - 1) ? g_scores[tid * B_SZ + b] : -1e30f;
    red[tid] = v;
    __syncthreads();
    for (int s = 256; s > 0; s >>= 1) {
        if (tid < s) red[tid] = fmaxf(red[tid], red[tid + s]);
        __syncthreads();
    }
    float m = red[0];
    __syncthreads();
    float e = (tid < S_LEN - 1) ? expf(v - m) : 0.f;
    red[tid] = e;
    __syncthreads();
    for (int s = 256; s > 0; s >>= 1) {
        if (tid < s) red[tid] += red[tid + s];
        __syncthreads();
    }
    float inv = 1.f / red[0];
    if (tid < S_LEN - 1) g_attn[tid * B_SZ + b] = e * inv;
}

// ---- K3c: att_out ----
__global__ void __launch_bounds__(256) attout_kernel() {
    const int b = blockIdx.y;
    const int h = blockIdx.x * 256 + threadIdx.x;
    float acc = 0.f;
#pragma unroll 4
    for (int s = 0; s < S_LEN - 1; s++)
        acc += g_attn[s * B_SZ + b] * g_OUT[(size_t)s * B_SZ * HIDD + (size_t)b * HIDD + h];
    g_attout[b * HIDD + h] = acc;
}

// ---- K4: out GEMM ----
__global__ void __launch_bounds__(256) out_gemm_kernel(const float* __restrict__ W_out,
                                                       const float* __restrict__ b_out,
                                                       float* __restrict__ out) {
    __shared__ float2 Fs2[16 * 64];
    __shared__ float  Ws[16 * 132];
    const int n0 = blockIdx.x * 128;
    const int tid = threadIdx.x;
    const int tx = tid & 31, ty = tid >> 5;
    const float* last = g_OUT + (size_t)(S_LEN - 1) * B_SZ * HIDD;

    unsigned long long acc[8][2];
#pragma unroll
    for (int i = 0; i < 8; i++) { acc[i][0] = 0ull; acc[i][1] = 0ull; }

    const int mm = tid >> 2;
    const int kq = (tid & 3) * 4;

    for (int k0 = 0; k0 < FEATD; k0 += 16) {
        int k = k0 + kq;
        const float* src = (k < HIDD) ? &g_attout[mm * HIDD + k]
                                      : &last[(size_t)mm * HIDD + (k - HIDD)];
        float4 fv = *(const float4*)src;
        Fs2[(kq + 0) * 64 + mm] = make_float2(fv.x, fv.x);
        Fs2[(kq + 1) * 64 + mm] = make_float2(fv.y, fv.y);
        Fs2[(kq + 2) * 64 + mm] = make_float2(fv.z, fv.z);
        Fs2[(kq + 3) * 64 + mm] = make_float2(fv.w, fv.w);
#pragma unroll
        for (int r = 0; r < 2; r++) {
            int f = tid + r * 256;
            int nn = f >> 2;
            int kq2 = (f & 3) * 4;
            float4 wv = *(const float4*)&W_out[(size_t)(n0 + nn) * FEATD + k0 + kq2];
            Ws[(kq2 + 0) * 132 + nn] = wv.x; Ws[(kq2 + 1) * 132 + nn] = wv.y;
            Ws[(kq2 + 2) * 132 + nn] = wv.z; Ws[(kq2 + 3) * 132 + nn] = wv.w;
        }
        __syncthreads();
#pragma unroll
        for (int kk = 0; kk < 16; kk++) {
            ulonglong2 a01 = *(const ulonglong2*)&Fs2[kk * 64 + ty * 8];
            ulonglong2 a23 = *(const ulonglong2*)&Fs2[kk * 64 + ty * 8 + 2];
            ulonglong2 a45 = *(const ulonglong2*)&Fs2[kk * 64 + ty * 8 + 4];
            ulonglong2 a67 = *(const ulonglong2*)&Fs2[kk * 64 + ty * 8 + 6];
            ulonglong2 wp  = *(const ulonglong2*)&Ws[kk * 132 + tx * 4];
            FFMA2(acc[0][0], a01.x, wp.x); FFMA2(acc[0][1], a01.x, wp.y);
            FFMA2(acc[1][0], a01.y, wp.x); FFMA2(acc[1][1], a01.y, wp.y);
            FFMA2(acc[2][0], a23.x, wp.x); FFMA2(acc[2][1], a23.x, wp.y);
            FFMA2(acc[3][0], a23.y, wp.x); FFMA2(acc[3][1], a23.y, wp.y);
            FFMA2(acc[4][0], a45.x, wp.x); FFMA2(acc[4][1], a45.x, wp.y);
            FFMA2(acc[5][0], a45.y, wp.x); FFMA2(acc[5][1], a45.y, wp.y);
            FFMA2(acc[6][0], a67.x, wp.x); FFMA2(acc[6][1], a67.x, wp.y);
            FFMA2(acc[7][0], a67.y, wp.x); FFMA2(acc[7][1], a67.y, wp.y);
        }
        __syncthreads();
    }
    float4 bo = *(const float4*)&b_out[n0 + tx * 4];
#pragma unroll
    for (int i = 0; i < 8; i++) {
        int m = ty * 8 + i;
        F2U p0, p1; p0.u = acc[i][0]; p1.u = acc[i][1];
        float4 o = make_float4(p0.f.x + bo.x, p0.f.y + bo.y,
                               p1.f.x + bo.z, p1.f.y + bo.w);
        *(float4*)&out[(size_t)m * NCLS + n0 + tx * 4] = o;
    }
}

// ---- launch ----
extern "C" void kernel_launch(void* const* d_in, const int* in_sizes, int n_in,
                              void* d_out, int out_size) {
    (void)in_sizes; (void)n_in; (void)out_size;
    const int*   X     = (const int*)d_in[0];
    const float* emb   = (const float*)d_in[1];
    const float* W_ih  = (const float*)d_in[2];
    const float* W_hh  = (const float*)d_in[3];
    const float* b_ih  = (const float*)d_in[4];
    const float* b_hh  = (const float*)d_in[5];
    const float* W_out = (const float*)d_in[6];
    const float* b_out = (const float*)d_in[7];
    float* out = (float*)d_out;

    static bool attr_set = false;
    if (!attr_set) {
        cudaFuncSetAttribute(rnn_kernel, cudaFuncAttributeMaxDynamicSharedMemorySize, RNN_SMEM);
        attr_set = true;
    }

    init_kernel<<<256, 256>>>();
    gates_kernel<<<dim3(HIDD / 64, (S_LEN * B_SZ) / 64), 256>>>(X, emb, W_ih, b_ih, b_hh);
    rnn_kernel<<<RNN_NCTA, 128, RNN_SMEM>>>(W_hh);
    scores_kernel<<<S_LEN - 1, 256>>>();
    softmax_kernel<<<B_SZ, 512>>>();
    attout_kernel<<<dim3(HIDD / 256, B_SZ), 256>>>();
    out_gemm_kernel<<<NCLS / 128, 256>>>(W_out, b_out, out);
}